// round 14
// baseline (speedup 1.0000x reference)
#include <cuda_runtime.h>
#include <cuda_bf16.h>
#include <math.h>
#include <stdint.h>

#define BB   4
#define SS   4096
#define DDIM 1024
#define HH   8
#define MM   (BB * SS)          // 16384
#define NM   (MM * DDIM)        // 16777216
#define NCHUNK 8
#define CHUNK_S 512
#define SCALE 0.08838834764831845f   // 1/sqrt(128)

// tensor GEMM tiling
#define BK 32
#define NK (DDIM / BK)          // 32 mainloop iters
#define NSTAGE 3
#define TILE_BYTES (128 * 64)   // 128 rows x 32 bf16 = 8192 B
#define STAGE_BYTES (4 * TILE_BYTES)    // Ah, Al, Wh, Wl
#define SMEM_DYN (NSTAGE * STAGE_BYTES + 128)

// ---------------- scratch ----------------
__device__ float g_proj[4 * NM];            // q,k,v,gate fp32
__device__ __nv_bfloat16 g_hsh[NM];
__device__ __nv_bfloat16 g_hsl[NM];
__device__ __nv_bfloat16 g_oh[NM];
__device__ __nv_bfloat16 g_ol[NM];
__device__ __nv_bfloat16 g_wh[5 * DDIM * DDIM];
__device__ __nv_bfloat16 g_wl[5 * DDIM * DDIM];
__device__ float g_kvp[BB * HH * NCHUNK * 128 * 128];
__device__ float g_ksump[BB * HH * NCHUNK * 128];
__device__ float g_vsump[BB * HH * NCHUNK * 128];
__device__ float g_kv[BB * HH * 128 * 128];
__device__ float g_ksum[BB * HH * 128];
__device__ float g_vsum[BB * HH * 128];
__device__ float g_sintab[SS * 64];
__device__ float g_costab[SS * 64];

// ---------------- PTX helpers (baseline ISA only: sm_80+) ----------------
__device__ __forceinline__ uint32_t smem_u32(const void* p) {
    uint32_t a;
    asm("{ .reg .u64 t; cvta.to.shared.u64 t, %1; cvt.u32.u64 %0, t; }" : "=r"(a) : "l"(p));
    return a;
}
#define CP_ASYNC16(dst, src) \
    asm volatile("cp.async.cg.shared.global [%0], [%1], 16;" :: "r"(dst), "l"(src))
#define CP_COMMIT() asm volatile("cp.async.commit_group;" ::: "memory")
#define CP_WAIT(n)  asm volatile("cp.async.wait_group %0;" :: "n"(n) : "memory")
#define LDSM_X4(r0, r1, r2, r3, addr) \
    asm volatile("ldmatrix.sync.aligned.m8n8.x4.shared.b16 {%0,%1,%2,%3}, [%4];" \
                 : "=r"(r0), "=r"(r1), "=r"(r2), "=r"(r3) : "r"(addr))
#define MMA16816(c0, c1, c2, c3, a0, a1, a2, a3, b0, b1) \
    asm volatile("mma.sync.aligned.m16n8k16.row.col.f32.bf16.bf16.f32 " \
                 "{%0,%1,%2,%3}, {%4,%5,%6,%7}, {%8,%9}, {%0,%1,%2,%3};" \
                 : "+f"(c0), "+f"(c1), "+f"(c2), "+f"(c3) \
                 : "r"(a0), "r"(a1), "r"(a2), "r"(a3), "r"(b0), "r"(b1))

// swizzled 16B-unit offset inside a 128x32-bf16 tile (row stride 64B, 4 chunks/row)
__device__ __forceinline__ uint32_t tile_off(int row, int chunk) {
    return (uint32_t)(row * 64 + ((chunk ^ (row & 3)) << 4));
}

// ---------------- fp32 -> bf16 hi/lo split ----------------
__device__ __forceinline__ void split_body(const float* __restrict__ x,
                                           __nv_bfloat16* __restrict__ hi,
                                           __nv_bfloat16* __restrict__ lo, int i)
{
    float4 v = reinterpret_cast<const float4*>(x)[i];
    __nv_bfloat16 h0 = __float2bfloat16(v.x), h1 = __float2bfloat16(v.y);
    __nv_bfloat16 h2 = __float2bfloat16(v.z), h3 = __float2bfloat16(v.w);
    __nv_bfloat16 l0 = __float2bfloat16(v.x - __bfloat162float(h0));
    __nv_bfloat16 l1 = __float2bfloat16(v.y - __bfloat162float(h1));
    __nv_bfloat16 l2 = __float2bfloat16(v.z - __bfloat162float(h2));
    __nv_bfloat16 l3 = __float2bfloat16(v.w - __bfloat162float(h3));
    __nv_bfloat162* hp = reinterpret_cast<__nv_bfloat162*>(hi) + i * 2;
    __nv_bfloat162* lp = reinterpret_cast<__nv_bfloat162*>(lo) + i * 2;
    hp[0] = __nv_bfloat162(h0, h1); hp[1] = __nv_bfloat162(h2, h3);
    lp[0] = __nv_bfloat162(l0, l1); lp[1] = __nv_bfloat162(l2, l3);
}

__global__ void split_kernel(const float* __restrict__ x, __nv_bfloat16* __restrict__ hi,
                             __nv_bfloat16* __restrict__ lo, int n4)
{
    int i = blockIdx.x * 256 + threadIdx.x;
    if (i >= n4) return;
    split_body(x, hi, lo, i);
}

// two matrices per launch (blockIdx.y selects)
__global__ void split2_kernel(const float* __restrict__ x0, const float* __restrict__ x1,
                              __nv_bfloat16* __restrict__ h0, __nv_bfloat16* __restrict__ l0,
                              __nv_bfloat16* __restrict__ h1, __nv_bfloat16* __restrict__ l1,
                              int n4)
{
    int i = blockIdx.x * 256 + threadIdx.x;
    if (i >= n4) return;
    if (blockIdx.y == 0) split_body(x0, h0, l0, i);
    else                 split_body(x1, h1, l1, i);
}

// ---------------- RoPE table ----------------
__global__ void rope_table_kernel(float* __restrict__ sintab, float* __restrict__ costab)
{
    int idx = blockIdx.x * 256 + threadIdx.x;
    if (idx >= SS * 64) return;
    int s = idx >> 6;
    int j = idx & 63;
    double invf = exp(-(double)j * (9.210340371976184 / 64.0));
    double ang = (double)s * invf;
    double sad, cad;
    sincos(ang, &sad, &cad);
    sintab[idx] = (float)sad;
    costab[idx] = (float)cad;
}

// ---------------- mma.sync split-bf16 GEMM with optional fused RoPE epilogue ----------------
// C[m,n] = sum_k A[m,k] * W[n,k]; grid (DDIM/128, MM/128, nz).
// rope_mask bit z => apply RoPE rotation in epilogue (valid because a 128-wide
// n-tile is exactly one head: j and j+64 are both inside the tile).
__global__ __launch_bounds__(256, 2) void gemm_tc_kernel(
    const __nv_bfloat16* __restrict__ Ah, const __nv_bfloat16* __restrict__ Al,
    const __nv_bfloat16* __restrict__ Wh0, const __nv_bfloat16* __restrict__ Wl0,
    float* __restrict__ C0, int rope_mask,
    const float* __restrict__ sintab, const float* __restrict__ costab)
{
    extern __shared__ char dynsmem[];
    const int tid = threadIdx.x;
    const int wid = tid >> 5;
    const int lane = tid & 31;
    const int bm = blockIdx.y * 128;
    const int bn = blockIdx.x * 128;
    const int z = blockIdx.z;
    const __nv_bfloat16* Wh = Wh0 + (size_t)z * DDIM * DDIM;
    const __nv_bfloat16* Wl = Wl0 + (size_t)z * DDIM * DDIM;
    float* C = C0 + (size_t)z * NM;

    const uint32_t S = (smem_u32(dynsmem) + 127u) & ~127u;

    // per-thread cp.async slots: 2 chunk-slots per tile (512 slots / 256 thr)
    const int slot0 = tid, slot1 = tid + 256;
    const int r0 = slot0 >> 2, c0 = slot0 & 3;
    const int r1 = slot1 >> 2, c1 = slot1 & 3;
    const uint32_t d0 = tile_off(r0, c0);
    const uint32_t d1 = tile_off(r1, c1);

    const int wm = (wid >> 2) * 64;     // warp M base (0/64)
    const int wn = (wid & 3) * 32;      // warp N base (0/32/64/96)

    float c[4][4][4];
#pragma unroll
    for (int i = 0; i < 4; i++)
#pragma unroll
        for (int j = 0; j < 4; j++)
#pragma unroll
            for (int k = 0; k < 4; k++) c[i][j][k] = 0.f;

    // prologue: load stages 0 and 1
#pragma unroll
    for (int st = 0; st < 2; st++) {
        const uint32_t sb = S + st * STAGE_BYTES;
        CP_ASYNC16(sb + d0, Ah + (size_t)(bm + r0) * DDIM + st * BK + c0 * 8);
        CP_ASYNC16(sb + d1, Ah + (size_t)(bm + r1) * DDIM + st * BK + c1 * 8);
        CP_ASYNC16(sb + TILE_BYTES + d0, Al + (size_t)(bm + r0) * DDIM + st * BK + c0 * 8);
        CP_ASYNC16(sb + TILE_BYTES + d1, Al + (size_t)(bm + r1) * DDIM + st * BK + c1 * 8);
        CP_ASYNC16(sb + 2 * TILE_BYTES + d0, Wh + (size_t)(bn + r0) * DDIM + st * BK + c0 * 8);
        CP_ASYNC16(sb + 2 * TILE_BYTES + d1, Wh + (size_t)(bn + r1) * DDIM + st * BK + c1 * 8);
        CP_ASYNC16(sb + 3 * TILE_BYTES + d0, Wl + (size_t)(bn + r0) * DDIM + st * BK + c0 * 8);
        CP_ASYNC16(sb + 3 * TILE_BYTES + d1, Wl + (size_t)(bn + r1) * DDIM + st * BK + c1 * 8);
        CP_COMMIT();
    }

    // ldmatrix address components
    const int a_row_lo = lane & 15;          // row within m16
    const int a_chunk_hi = lane >> 4;        // k-half select
    // B x4: lane groups 0-3 address matrices (nt,b0),(nt,b1),(nt+1,b0),(nt+1,b1)
    const int b4_row = ((lane >> 4) << 3) + (lane & 7);  // +8 rows for groups 2,3
    const int b4_chunk = (lane >> 3) & 1;                // +1 chunk for odd groups

#pragma unroll 1
    for (int i = 0; i < NK; i++) {
        __syncthreads();   // all warps done computing stage i-1 (buffer (i+2)%3)
        if (i + 2 < NK) {
            const int st = i + 2;
            const uint32_t sb = S + (st % NSTAGE) * STAGE_BYTES;
            CP_ASYNC16(sb + d0, Ah + (size_t)(bm + r0) * DDIM + st * BK + c0 * 8);
            CP_ASYNC16(sb + d1, Ah + (size_t)(bm + r1) * DDIM + st * BK + c1 * 8);
            CP_ASYNC16(sb + TILE_BYTES + d0, Al + (size_t)(bm + r0) * DDIM + st * BK + c0 * 8);
            CP_ASYNC16(sb + TILE_BYTES + d1, Al + (size_t)(bm + r1) * DDIM + st * BK + c1 * 8);
            CP_ASYNC16(sb + 2 * TILE_BYTES + d0, Wh + (size_t)(bn + r0) * DDIM + st * BK + c0 * 8);
            CP_ASYNC16(sb + 2 * TILE_BYTES + d1, Wh + (size_t)(bn + r1) * DDIM + st * BK + c1 * 8);
            CP_ASYNC16(sb + 3 * TILE_BYTES + d0, Wl + (size_t)(bn + r0) * DDIM + st * BK + c0 * 8);
            CP_ASYNC16(sb + 3 * TILE_BYTES + d1, Wl + (size_t)(bn + r1) * DDIM + st * BK + c1 * 8);
            CP_COMMIT();
            CP_WAIT(2);
        } else if (i + 1 < NK) {
            CP_WAIT(1);
        } else {
            CP_WAIT(0);
        }
        __syncthreads();   // stage i visible to all

        const uint32_t sb = S + (i % NSTAGE) * STAGE_BYTES;
        const uint32_t sAh = sb, sAl = sb + TILE_BYTES;
        const uint32_t sWh = sb + 2 * TILE_BYTES, sWl = sb + 3 * TILE_BYTES;

#pragma unroll
        for (int k16 = 0; k16 < 2; k16++) {
            uint32_t ah[4][4], al[4][4];
#pragma unroll
            for (int mt = 0; mt < 4; mt++) {
                int row = wm + mt * 16 + a_row_lo;
                uint32_t off = tile_off(row, k16 * 2 + a_chunk_hi);
                LDSM_X4(ah[mt][0], ah[mt][1], ah[mt][2], ah[mt][3], sAh + off);
                LDSM_X4(al[mt][0], al[mt][1], al[mt][2], al[mt][3], sAl + off);
            }
            // B: one x4 covers nt pair (2p, 2p+1), both k-halves
#pragma unroll
            for (int p = 0; p < 2; p++) {
                int row = wn + p * 16 + b4_row;
                uint32_t off = tile_off(row, k16 * 2 + b4_chunk);
                uint32_t bh0, bh1, bh2, bh3, bl0, bl1, bl2, bl3;
                LDSM_X4(bh0, bh1, bh2, bh3, sWh + off);
                LDSM_X4(bl0, bl1, bl2, bl3, sWl + off);
#pragma unroll
                for (int q2 = 0; q2 < 2; q2++) {
                    int nt = p * 2 + q2;
                    uint32_t vbh0 = q2 ? bh2 : bh0, vbh1 = q2 ? bh3 : bh1;
                    uint32_t vbl0 = q2 ? bl2 : bl0, vbl1 = q2 ? bl3 : bl1;
#pragma unroll
                    for (int mt = 0; mt < 4; mt++) {
                        MMA16816(c[mt][nt][0], c[mt][nt][1], c[mt][nt][2], c[mt][nt][3],
                                 ah[mt][0], ah[mt][1], ah[mt][2], ah[mt][3], vbh0, vbh1);
                        MMA16816(c[mt][nt][0], c[mt][nt][1], c[mt][nt][2], c[mt][nt][3],
                                 ah[mt][0], ah[mt][1], ah[mt][2], ah[mt][3], vbl0, vbl1);
                        MMA16816(c[mt][nt][0], c[mt][nt][1], c[mt][nt][2], c[mt][nt][3],
                                 al[mt][0], al[mt][1], al[mt][2], al[mt][3], vbh0, vbh1);
                    }
                }
            }
        }
    }

    // epilogue
    const int erow = lane >> 2;
    const int ecol = (lane & 3) * 2;
    if ((rope_mask >> z) & 1) {
        // stage tile through smem, apply RoPE, store
        float* cs = reinterpret_cast<float*>(dynsmem);
        __syncthreads();  // mainloop smem reads done before overwrite
#pragma unroll
        for (int mt = 0; mt < 4; mt++) {
#pragma unroll
            for (int nt = 0; nt < 4; nt++) {
                int rr = wm + mt * 16 + erow;
                int cc = wn + nt * 8 + ecol;
                cs[rr * 128 + cc] = c[mt][nt][0];
                cs[rr * 128 + cc + 1] = c[mt][nt][1];
                cs[(rr + 8) * 128 + cc] = c[mt][nt][2];
                cs[(rr + 8) * 128 + cc + 1] = c[mt][nt][3];
            }
        }
        __syncthreads();
        for (int idx = tid; idx < 128 * 64; idx += 256) {
            int row = idx >> 6, j = idx & 63;
            int s = (bm + row) & (SS - 1);
            float sa = sintab[s * 64 + j];
            float ca = costab[s * 64 + j];
            float x1 = cs[row * 128 + j];
            float x2 = cs[row * 128 + j + 64];
            C[(size_t)(bm + row) * DDIM + bn + j] = x1 * ca - x2 * sa;
            C[(size_t)(bm + row) * DDIM + bn + j + 64] = x2 * ca + x1 * sa;
        }
    } else {
#pragma unroll
        for (int mt = 0; mt < 4; mt++) {
#pragma unroll
            for (int nt = 0; nt < 4; nt++) {
                int m = bm + wm + mt * 16 + erow;
                int n = bn + wn + nt * 8 + ecol;
                float* p0 = C + (size_t)m * DDIM + n;
                float* p1 = C + (size_t)(m + 8) * DDIM + n;
                *reinterpret_cast<float2*>(p0) = make_float2(c[mt][nt][0], c[mt][nt][1]);
                *reinterpret_cast<float2*>(p1) = make_float2(c[mt][nt][2], c[mt][nt][3]);
            }
        }
    }
}

// ---------------- kv partial: 512-row S chunks ----------------
__global__ __launch_bounds__(256) void kv_partial_kernel(
    const float* __restrict__ k, const float* __restrict__ v,
    float* __restrict__ kvp, float* __restrict__ ksump, float* __restrict__ vsump)
{
    const int bh = blockIdx.x;       // 0..31
    const int chunk = blockIdx.y;    // 0..7
    const int b = bh >> 3, h = bh & 7;
    const size_t rowbase = ((size_t)(b * SS + chunk * CHUNK_S)) * DDIM + h * 128;

    __shared__ float ks[16][128];
    __shared__ float vs[16][128];
    const int tid = threadIdx.x;
    const int ty = tid >> 4, tx = tid & 15;
    const int lr = tid >> 4;
    const int lc = (tid & 15) << 3;

    float acc[8][8];
#pragma unroll
    for (int i = 0; i < 8; i++)
#pragma unroll
        for (int j = 0; j < 8; j++) acc[i][j] = 0.f;
    float sacc = 0.f;

    for (int sc = 0; sc < CHUNK_S / 16; sc++) {
        size_t base = rowbase + (size_t)(sc * 16 + lr) * DDIM + lc;
        float4 ka = *reinterpret_cast<const float4*>(k + base);
        float4 kb2 = *reinterpret_cast<const float4*>(k + base + 4);
        ks[lr][lc + 0] = ka.x; ks[lr][lc + 1] = ka.y; ks[lr][lc + 2] = ka.z; ks[lr][lc + 3] = ka.w;
        ks[lr][lc + 4] = kb2.x; ks[lr][lc + 5] = kb2.y; ks[lr][lc + 6] = kb2.z; ks[lr][lc + 7] = kb2.w;
        float4 va = *reinterpret_cast<const float4*>(v + base);
        float4 vb2 = *reinterpret_cast<const float4*>(v + base + 4);
        vs[lr][lc + 0] = va.x; vs[lr][lc + 1] = va.y; vs[lr][lc + 2] = va.z; vs[lr][lc + 3] = va.w;
        vs[lr][lc + 4] = vb2.x; vs[lr][lc + 5] = vb2.y; vs[lr][lc + 6] = vb2.z; vs[lr][lc + 7] = vb2.w;
        __syncthreads();
#pragma unroll
        for (int ssi = 0; ssi < 16; ssi++) {
            float4 a0 = *reinterpret_cast<const float4*>(&ks[ssi][ty * 8]);
            float4 a1 = *reinterpret_cast<const float4*>(&ks[ssi][ty * 8 + 4]);
            float4 b0 = *reinterpret_cast<const float4*>(&vs[ssi][tx * 8]);
            float4 b1 = *reinterpret_cast<const float4*>(&vs[ssi][tx * 8 + 4]);
            float af[8] = {a0.x, a0.y, a0.z, a0.w, a1.x, a1.y, a1.z, a1.w};
            float bf[8] = {b0.x, b0.y, b0.z, b0.w, b1.x, b1.y, b1.z, b1.w};
#pragma unroll
            for (int i = 0; i < 8; i++)
#pragma unroll
                for (int j = 0; j < 8; j++) acc[i][j] += af[i] * bf[j];
        }
        if (tid < 128) {
#pragma unroll
            for (int ssi = 0; ssi < 16; ssi++) sacc += ks[ssi][tid];
        } else {
#pragma unroll
            for (int ssi = 0; ssi < 16; ssi++) sacc += vs[ssi][tid - 128];
        }
        __syncthreads();
    }

    size_t outbase = ((size_t)(bh * NCHUNK + chunk)) * 16384;
#pragma unroll
    for (int i = 0; i < 8; i++) {
        float* p = kvp + outbase + (size_t)(ty * 8 + i) * 128 + tx * 8;
        *reinterpret_cast<float4*>(p) = make_float4(acc[i][0], acc[i][1], acc[i][2], acc[i][3]);
        *reinterpret_cast<float4*>(p + 4) = make_float4(acc[i][4], acc[i][5], acc[i][6], acc[i][7]);
    }
    if (tid < 128) ksump[(bh * NCHUNK + chunk) * 128 + tid] = sacc;
    else           vsump[(bh * NCHUNK + chunk) * 128 + (tid - 128)] = sacc;
}

__global__ void kv_reduce_kernel(const float* __restrict__ kvp, float* __restrict__ kv)
{
    int bh = blockIdx.y;
    int idx = blockIdx.x * 256 + threadIdx.x;
    const float* p = kvp + (size_t)bh * NCHUNK * 16384 + idx;
    float s = 0.f;
#pragma unroll
    for (int c = 0; c < NCHUNK; c++) s += p[(size_t)c * 16384];
    kv[(size_t)bh * 16384 + idx] = s;
}

__global__ void sum_reduce_kernel(const float* __restrict__ ksump, const float* __restrict__ vsump,
                                  float* __restrict__ ksum, float* __restrict__ vsum)
{
    int bh = blockIdx.x;
    int t = threadIdx.x;
    if (t < 128) {
        float s = 0.f;
#pragma unroll
        for (int c = 0; c < NCHUNK; c++) s += ksump[(bh * NCHUNK + c) * 128 + t];
        ksum[bh * 128 + t] = s;
    } else {
        int e = t - 128;
        float s = 0.f;
#pragma unroll
        for (int c = 0; c < NCHUNK; c++) s += vsump[(bh * NCHUNK + c) * 128 + e];
        vsum[bh * 128 + e] = s;
    }
}

// ---------------- attention + LePE + gate; emits bf16 hi/lo directly ----------------
__global__ __launch_bounds__(256) void attn_kernel(
    const float* __restrict__ q, const float* __restrict__ v,
    const float* __restrict__ gate, const float* __restrict__ kv,
    const float* __restrict__ ksum, const float* __restrict__ vsum,
    const float* __restrict__ lw, const float* __restrict__ lb,
    __nv_bfloat16* __restrict__ oh, __nv_bfloat16* __restrict__ ol)
{
    const int stile = blockIdx.x;
    const int bh = blockIdx.y;
    const int half = blockIdx.z;
    const int b = bh >> 3, h = bh & 7;
    const int s0 = stile * 16;
    const int e0 = half * 64;

    __shared__ float kvs[128][64];
    __shared__ float qs[16][128];
    __shared__ float ksums[128];
    __shared__ float vsums[64];
    __shared__ float dens[16];

    const int tid = threadIdx.x;
    for (int i = tid; i < 128 * 16; i += 256) {
        int d = i >> 4, c = (i & 15) << 2;
        float4 t = *reinterpret_cast<const float4*>(kv + (size_t)bh * 16384 + d * 128 + e0 + c);
        kvs[d][c] = t.x; kvs[d][c + 1] = t.y; kvs[d][c + 2] = t.z; kvs[d][c + 3] = t.w;
    }
    for (int i = tid; i < 16 * 32; i += 256) {
        int r = i >> 5, c = (i & 31) << 2;
        float4 t = *reinterpret_cast<const float4*>(
            q + (((size_t)(b * SS + s0 + r)) * HH + h) * 128 + c);
        qs[r][c] = t.x; qs[r][c + 1] = t.y; qs[r][c + 2] = t.z; qs[r][c + 3] = t.w;
    }
    if (tid < 128) ksums[tid] = ksum[bh * 128 + tid];
    else if (tid < 192) vsums[tid - 128] = vsum[bh * 128 + e0 + (tid - 128)];
    __syncthreads();

    if (tid < 16) {
        float ds = 0.f;
#pragma unroll
        for (int d = 0; d < 128; d++) ds += qs[tid][d] * ksums[d];
        dens[tid] = ds * SCALE + (float)SS;
    }
    __syncthreads();

    const int ss = tid >> 4;
    const int e4 = (tid & 15) << 2;
    float acc0 = 0.f, acc1 = 0.f, acc2 = 0.f, acc3 = 0.f;
#pragma unroll 4
    for (int d = 0; d < 128; d++) {
        float qv = qs[ss][d];
        float4 kvv = *reinterpret_cast<const float4*>(&kvs[d][e4]);
        acc0 += qv * kvv.x;
        acc1 += qv * kvv.y;
        acc2 += qv * kvv.z;
        acc3 += qv * kvv.w;
    }

    const float invden = 1.0f / dens[ss];
    const int sg = s0 + ss;
    const int cbase = h * 128 + e0 + e4;

    float a0 = (acc0 * SCALE + vsums[e4 + 0]) * invden;
    float a1 = (acc1 * SCALE + vsums[e4 + 1]) * invden;
    float a2 = (acc2 * SCALE + vsums[e4 + 2]) * invden;
    float a3 = (acc3 * SCALE + vsums[e4 + 3]) * invden;

    float lep0 = lb[cbase + 0], lep1 = lb[cbase + 1], lep2 = lb[cbase + 2], lep3 = lb[cbase + 3];
#pragma unroll
    for (int t = 0; t < 5; t++) {
        int sp = sg + t - 2;
        if (sp >= 0 && sp < SS) {
            float4 vv = *reinterpret_cast<const float4*>(
                v + (((size_t)(b * SS + sp)) * HH + h) * 128 + e0 + e4);
            lep0 += vv.x * lw[(cbase + 0) * 5 + t];
            lep1 += vv.y * lw[(cbase + 1) * 5 + t];
            lep2 += vv.z * lw[(cbase + 2) * 5 + t];
            lep3 += vv.w * lw[(cbase + 3) * 5 + t];
        }
    }

    float4 g4 = *reinterpret_cast<const float4*>(gate + ((size_t)(b * SS + sg)) * DDIM + cbase);
    float r0 = (a0 + lep0) * g4.x;
    float r1 = (a1 + lep1) * g4.y;
    float r2 = (a2 + lep2) * g4.z;
    float r3 = (a3 + lep3) * g4.w;

    __nv_bfloat16 h0 = __float2bfloat16(r0), h1 = __float2bfloat16(r1);
    __nv_bfloat16 h2 = __float2bfloat16(r2), h3 = __float2bfloat16(r3);
    __nv_bfloat16 l0 = __float2bfloat16(r0 - __bfloat162float(h0));
    __nv_bfloat16 l1 = __float2bfloat16(r1 - __bfloat162float(h1));
    __nv_bfloat16 l2 = __float2bfloat16(r2 - __bfloat162float(h2));
    __nv_bfloat16 l3 = __float2bfloat16(r3 - __bfloat162float(h3));
    size_t obase = ((size_t)(b * SS + sg)) * DDIM + cbase;
    __nv_bfloat162* hp = reinterpret_cast<__nv_bfloat162*>(oh + obase);
    __nv_bfloat162* lp = reinterpret_cast<__nv_bfloat162*>(ol + obase);
    hp[0] = __nv_bfloat162(h0, h1); hp[1] = __nv_bfloat162(h2, h3);
    lp[0] = __nv_bfloat162(l0, l1); lp[1] = __nv_bfloat162(l2, l3);
}

// ---------------- host launch ----------------
extern "C" void kernel_launch(void* const* d_in, const int* in_sizes, int n_in,
                              void* d_out, int out_size)
{
    const float* hs = (const float*)d_in[0];
    const float* Wq = (const float*)d_in[1];
    const float* Wk = (const float*)d_in[2];
    const float* Wv = (const float*)d_in[3];
    const float* Wg = (const float*)d_in[4];
    const float* Wo = (const float*)d_in[5];
    const float* lw = (const float*)d_in[6];
    const float* lb = (const float*)d_in[7];
    float* out = (float*)d_out;

    float *projp, *kvpp, *kspp, *vspp, *kvfull, *ksp, *vsp, *stp, *ctp;
    __nv_bfloat16 *hsh, *hsl, *oh, *ol, *wh, *wl;
    cudaGetSymbolAddress((void**)&projp, g_proj);
    cudaGetSymbolAddress((void**)&kvpp, g_kvp);
    cudaGetSymbolAddress((void**)&kspp, g_ksump);
    cudaGetSymbolAddress((void**)&vspp, g_vsump);
    cudaGetSymbolAddress((void**)&kvfull, g_kv);
    cudaGetSymbolAddress((void**)&ksp, g_ksum);
    cudaGetSymbolAddress((void**)&vsp, g_vsum);
    cudaGetSymbolAddress((void**)&hsh, g_hsh);
    cudaGetSymbolAddress((void**)&hsl, g_hsl);
    cudaGetSymbolAddress((void**)&oh, g_oh);
    cudaGetSymbolAddress((void**)&ol, g_ol);
    cudaGetSymbolAddress((void**)&wh, g_wh);
    cudaGetSymbolAddress((void**)&wl, g_wl);
    cudaGetSymbolAddress((void**)&stp, g_sintab);
    cudaGetSymbolAddress((void**)&ctp, g_costab);

    static int smem_set = 0;
    if (!smem_set) {
        cudaFuncSetAttribute(gemm_tc_kernel, cudaFuncAttributeMaxDynamicSharedMemorySize, SMEM_DYN);
        smem_set = 1;
    }

    float* qp = projp;
    float* kp = projp + (size_t)NM;
    float* vp = projp + 2 * (size_t)NM;
    float* gp = projp + 3 * (size_t)NM;

    const int WN4 = DDIM * DDIM / 4;
    const size_t WSZ = (size_t)DDIM * DDIM;
    // launch order arranged so gemm_qkvg is launch #6 (ncu -s 5 -c 1 captures it)
    rope_table_kernel<<<(SS * 64 + 255) / 256, 256>>>(stp, ctp);                       // 1
    split_kernel<<<NM / 4 / 256, 256>>>(hs, hsh, hsl, NM / 4);                         // 2
    split2_kernel<<<dim3(WN4 / 256, 2), 256>>>(Wq, Wk, wh, wl, wh + WSZ, wl + WSZ, WN4);          // 3
    split2_kernel<<<dim3(WN4 / 256, 2), 256>>>(Wv, Wg, wh + 2 * WSZ, wl + 2 * WSZ,
                                               wh + 3 * WSZ, wl + 3 * WSZ, WN4);       // 4
    split_kernel<<<WN4 / 256, 256>>>(Wo, wh + 4 * WSZ, wl + 4 * WSZ, WN4);             // 5

    // QKVG projection + fused RoPE on q (z=0), k (z=1)
    gemm_tc_kernel<<<dim3(DDIM / 128, MM / 128, 4), 256, SMEM_DYN>>>(                  // 6
        hsh, hsl, wh, wl, projp, 0b0011, stp, ctp);

    kv_partial_kernel<<<dim3(BB * HH, NCHUNK), 256>>>(kp, vp, kvpp, kspp, vspp);       // 7
    kv_reduce_kernel<<<dim3(64, BB * HH), 256>>>(kvpp, kvfull);                        // 8
    sum_reduce_kernel<<<BB * HH, 256>>>(kspp, vspp, ksp, vsp);                         // 9

    attn_kernel<<<dim3(SS / 16, BB * HH, 2), 256>>>(qp, vp, gp, kvfull, ksp, vsp, lw, lb, oh, ol); // 10

    gemm_tc_kernel<<<dim3(DDIM / 128, MM / 128, 1), 256, SMEM_DYN>>>(                  // 11
        oh, ol, wh + 4 * WSZ, wl + 4 * WSZ, out, 0, stp, ctp);
}

// round 17
// speedup vs baseline: 1.5911x; 1.5911x over previous
#include <cuda_runtime.h>
#include <cuda_bf16.h>
#include <math.h>
#include <stdint.h>

#define BB   4
#define SS   4096
#define DDIM 1024
#define HH   8
#define MM   (BB * SS)          // 16384
#define NM   (MM * DDIM)        // 16777216
#define NCHUNK 8
#define CHUNK_S 512
#define SCALE 0.08838834764831845f   // 1/sqrt(128)

// tensor GEMM tiling
#define BK 32
#define NK (DDIM / BK)          // 32 mainloop iters
#define NSTAGE 3
#define TILE_BYTES (128 * 64)   // 128 rows x 32 bf16 = 8192 B
#define STAGE_BYTES (4 * TILE_BYTES)    // Ah, Al, Wh, Wl
#define SMEM_DYN (NSTAGE * STAGE_BYTES + 128)

// ---------------- scratch ----------------
__device__ float g_proj[4 * NM];            // q,k,v,gate fp32
__device__ __nv_bfloat16 g_hsh[NM];
__device__ __nv_bfloat16 g_hsl[NM];
__device__ __nv_bfloat16 g_oh[NM];
__device__ __nv_bfloat16 g_ol[NM];
__device__ __nv_bfloat16 g_wh[5 * DDIM * DDIM];
__device__ __nv_bfloat16 g_wl[5 * DDIM * DDIM];
__device__ float g_kvp[BB * HH * NCHUNK * 128 * 128];
__device__ float g_ksump[BB * HH * NCHUNK * 128];
__device__ float g_vsump[BB * HH * NCHUNK * 128];
__device__ float g_kv[BB * HH * 128 * 128];
__device__ float g_ksum[BB * HH * 128];
__device__ float g_vsum[BB * HH * 128];
__device__ float g_sintab[SS * 64];
__device__ float g_costab[SS * 64];

// ---------------- PTX helpers (baseline ISA only: sm_80+) ----------------
__device__ __forceinline__ uint32_t smem_u32(const void* p) {
    uint32_t a;
    asm("{ .reg .u64 t; cvta.to.shared.u64 t, %1; cvt.u32.u64 %0, t; }" : "=r"(a) : "l"(p));
    return a;
}
#define CP_ASYNC16(dst, src) \
    asm volatile("cp.async.cg.shared.global [%0], [%1], 16;" :: "r"(dst), "l"(src))
#define CP_COMMIT() asm volatile("cp.async.commit_group;" ::: "memory")
#define CP_WAIT(n)  asm volatile("cp.async.wait_group %0;" :: "n"(n) : "memory")
#define LDSM_X4(r0, r1, r2, r3, addr) \
    asm volatile("ldmatrix.sync.aligned.m8n8.x4.shared.b16 {%0,%1,%2,%3}, [%4];" \
                 : "=r"(r0), "=r"(r1), "=r"(r2), "=r"(r3) : "r"(addr))
#define LDSM_X2(r0, r1, addr) \
    asm volatile("ldmatrix.sync.aligned.m8n8.x2.shared.b16 {%0,%1}, [%2];" \
                 : "=r"(r0), "=r"(r1) : "r"(addr))
#define MMA16816(c0, c1, c2, c3, a0, a1, a2, a3, b0, b1) \
    asm volatile("mma.sync.aligned.m16n8k16.row.col.f32.bf16.bf16.f32 " \
                 "{%0,%1,%2,%3}, {%4,%5,%6,%7}, {%8,%9}, {%0,%1,%2,%3};" \
                 : "+f"(c0), "+f"(c1), "+f"(c2), "+f"(c3) \
                 : "r"(a0), "r"(a1), "r"(a2), "r"(a3), "r"(b0), "r"(b1))

// swizzled 16B-unit offset inside a 128x32-bf16 tile (row stride 64B, 4 chunks/row)
__device__ __forceinline__ uint32_t tile_off(int row, int chunk) {
    return (uint32_t)(row * 64 + ((chunk ^ (row & 3)) << 4));
}

// ---------------- fp32 -> bf16 hi/lo split ----------------
__device__ __forceinline__ void split_body(const float* __restrict__ x,
                                           __nv_bfloat16* __restrict__ hi,
                                           __nv_bfloat16* __restrict__ lo, int i)
{
    float4 v = reinterpret_cast<const float4*>(x)[i];
    __nv_bfloat16 h0 = __float2bfloat16(v.x), h1 = __float2bfloat16(v.y);
    __nv_bfloat16 h2 = __float2bfloat16(v.z), h3 = __float2bfloat16(v.w);
    __nv_bfloat16 l0 = __float2bfloat16(v.x - __bfloat162float(h0));
    __nv_bfloat16 l1 = __float2bfloat16(v.y - __bfloat162float(h1));
    __nv_bfloat16 l2 = __float2bfloat16(v.z - __bfloat162float(h2));
    __nv_bfloat16 l3 = __float2bfloat16(v.w - __bfloat162float(h3));
    __nv_bfloat162* hp = reinterpret_cast<__nv_bfloat162*>(hi) + i * 2;
    __nv_bfloat162* lp = reinterpret_cast<__nv_bfloat162*>(lo) + i * 2;
    hp[0] = __nv_bfloat162(h0, h1); hp[1] = __nv_bfloat162(h2, h3);
    lp[0] = __nv_bfloat162(l0, l1); lp[1] = __nv_bfloat162(l2, l3);
}

__global__ void split_kernel(const float* __restrict__ x, __nv_bfloat16* __restrict__ hi,
                             __nv_bfloat16* __restrict__ lo, int n4)
{
    int i = blockIdx.x * 256 + threadIdx.x;
    if (i >= n4) return;
    split_body(x, hi, lo, i);
}

// two matrices per launch (blockIdx.y selects)
__global__ void split2_kernel(const float* __restrict__ x0, const float* __restrict__ x1,
                              __nv_bfloat16* __restrict__ h0, __nv_bfloat16* __restrict__ l0,
                              __nv_bfloat16* __restrict__ h1, __nv_bfloat16* __restrict__ l1,
                              int n4)
{
    int i = blockIdx.x * 256 + threadIdx.x;
    if (i >= n4) return;
    if (blockIdx.y == 0) split_body(x0, h0, l0, i);
    else                 split_body(x1, h1, l1, i);
}

// ---------------- RoPE table ----------------
__global__ void rope_table_kernel(float* __restrict__ sintab, float* __restrict__ costab)
{
    int idx = blockIdx.x * 256 + threadIdx.x;
    if (idx >= SS * 64) return;
    int s = idx >> 6;
    int j = idx & 63;
    double invf = exp(-(double)j * (9.210340371976184 / 64.0));
    double ang = (double)s * invf;
    double sad, cad;
    sincos(ang, &sad, &cad);
    sintab[idx] = (float)sad;
    costab[idx] = (float)cad;
}

// ---------------- RoPE in-place on q and k (table lookup) ----------------
__global__ void rope_kernel(float* __restrict__ q, float* __restrict__ k,
                            const float* __restrict__ sintab, const float* __restrict__ costab)
{
    int idx = blockIdx.x * blockDim.x + threadIdx.x;
    const int total = MM * HH * 64;
    if (idx >= total) return;
    int j = idx & 63;
    int rest = idx >> 6;                 // (b*S+s)*H + h
    int s = (rest >> 3) & (SS - 1);
    size_t base = (size_t)rest * 128;

    float sa = sintab[s * 64 + j];
    float ca = costab[s * 64 + j];

    float qx1 = q[base + j], qx2 = q[base + j + 64];
    q[base + j]      = qx1 * ca - qx2 * sa;
    q[base + j + 64] = qx2 * ca + qx1 * sa;

    float kx1 = k[base + j], kx2 = k[base + j + 64];
    k[base + j]      = kx1 * ca - kx2 * sa;
    k[base + j + 64] = kx2 * ca + kx1 * sa;
}

// ---------------- mma.sync split-bf16 GEMM: C[m,n] = sum_k A[m,k] * W[n,k] ----------------
// grid: (DDIM/128, MM/128, nz); A shared across z, W/C offset by z.
// (verified Round-13 version)
__global__ __launch_bounds__(256, 2) void gemm_tc_kernel(
    const __nv_bfloat16* __restrict__ Ah, const __nv_bfloat16* __restrict__ Al,
    const __nv_bfloat16* __restrict__ Wh0, const __nv_bfloat16* __restrict__ Wl0,
    float* __restrict__ C0)
{
    extern __shared__ char dynsmem[];
    const int tid = threadIdx.x;
    const int wid = tid >> 5;
    const int lane = tid & 31;
    const int bm = blockIdx.y * 128;
    const int bn = blockIdx.x * 128;
    const int z = blockIdx.z;
    const __nv_bfloat16* Wh = Wh0 + (size_t)z * DDIM * DDIM;
    const __nv_bfloat16* Wl = Wl0 + (size_t)z * DDIM * DDIM;
    float* C = C0 + (size_t)z * NM;

    const uint32_t S = (smem_u32(dynsmem) + 127u) & ~127u;

    // per-thread cp.async slots: 2 chunk-slots per tile (512 slots / 256 thr)
    const int slot0 = tid, slot1 = tid + 256;
    const int r0 = slot0 >> 2, c0 = slot0 & 3;
    const int r1 = slot1 >> 2, c1 = slot1 & 3;
    const uint32_t d0 = tile_off(r0, c0);
    const uint32_t d1 = tile_off(r1, c1);

    const int wm = (wid >> 2) * 64;     // warp M base (0/64)
    const int wn = (wid & 3) * 32;      // warp N base (0/32/64/96)

    float c[4][4][4];
#pragma unroll
    for (int i = 0; i < 4; i++)
#pragma unroll
        for (int j = 0; j < 4; j++)
#pragma unroll
            for (int k = 0; k < 4; k++) c[i][j][k] = 0.f;

    // prologue: load stages 0 and 1
#pragma unroll
    for (int st = 0; st < 2; st++) {
        const uint32_t sb = S + st * STAGE_BYTES;
        CP_ASYNC16(sb + d0, Ah + (size_t)(bm + r0) * DDIM + st * BK + c0 * 8);
        CP_ASYNC16(sb + d1, Ah + (size_t)(bm + r1) * DDIM + st * BK + c1 * 8);
        CP_ASYNC16(sb + TILE_BYTES + d0, Al + (size_t)(bm + r0) * DDIM + st * BK + c0 * 8);
        CP_ASYNC16(sb + TILE_BYTES + d1, Al + (size_t)(bm + r1) * DDIM + st * BK + c1 * 8);
        CP_ASYNC16(sb + 2 * TILE_BYTES + d0, Wh + (size_t)(bn + r0) * DDIM + st * BK + c0 * 8);
        CP_ASYNC16(sb + 2 * TILE_BYTES + d1, Wh + (size_t)(bn + r1) * DDIM + st * BK + c1 * 8);
        CP_ASYNC16(sb + 3 * TILE_BYTES + d0, Wl + (size_t)(bn + r0) * DDIM + st * BK + c0 * 8);
        CP_ASYNC16(sb + 3 * TILE_BYTES + d1, Wl + (size_t)(bn + r1) * DDIM + st * BK + c1 * 8);
        CP_COMMIT();
    }

    // ldmatrix address components
    const int a_row_lo = lane & 15;         // row within m16
    const int a_chunk_hi = lane >> 4;       // k-half select
    const int b_row_lo = lane & 7;          // n-row within n8
    const int b_chunk_hi = (lane >> 3) & 1; // k-half select (lanes 0-15 used by x2)

#pragma unroll 1
    for (int i = 0; i < NK; i++) {
        __syncthreads();   // all warps done computing stage i-1 (buffer (i+2)%3)
        if (i + 2 < NK) {
            const int st = i + 2;
            const uint32_t sb = S + (st % NSTAGE) * STAGE_BYTES;
            CP_ASYNC16(sb + d0, Ah + (size_t)(bm + r0) * DDIM + st * BK + c0 * 8);
            CP_ASYNC16(sb + d1, Ah + (size_t)(bm + r1) * DDIM + st * BK + c1 * 8);
            CP_ASYNC16(sb + TILE_BYTES + d0, Al + (size_t)(bm + r0) * DDIM + st * BK + c0 * 8);
            CP_ASYNC16(sb + TILE_BYTES + d1, Al + (size_t)(bm + r1) * DDIM + st * BK + c1 * 8);
            CP_ASYNC16(sb + 2 * TILE_BYTES + d0, Wh + (size_t)(bn + r0) * DDIM + st * BK + c0 * 8);
            CP_ASYNC16(sb + 2 * TILE_BYTES + d1, Wh + (size_t)(bn + r1) * DDIM + st * BK + c1 * 8);
            CP_ASYNC16(sb + 3 * TILE_BYTES + d0, Wl + (size_t)(bn + r0) * DDIM + st * BK + c0 * 8);
            CP_ASYNC16(sb + 3 * TILE_BYTES + d1, Wl + (size_t)(bn + r1) * DDIM + st * BK + c1 * 8);
            CP_COMMIT();
            CP_WAIT(2);
        } else if (i + 1 < NK) {
            CP_WAIT(1);
        } else {
            CP_WAIT(0);
        }
        __syncthreads();   // stage i visible to all

        const uint32_t sb = S + (i % NSTAGE) * STAGE_BYTES;
        const uint32_t sAh = sb, sAl = sb + TILE_BYTES;
        const uint32_t sWh = sb + 2 * TILE_BYTES, sWl = sb + 3 * TILE_BYTES;

#pragma unroll
        for (int k16 = 0; k16 < 2; k16++) {
            uint32_t ah[4][4], al[4][4];
#pragma unroll
            for (int mt = 0; mt < 4; mt++) {
                int row = wm + mt * 16 + a_row_lo;
                uint32_t off = tile_off(row, k16 * 2 + a_chunk_hi);
                LDSM_X4(ah[mt][0], ah[mt][1], ah[mt][2], ah[mt][3], sAh + off);
                LDSM_X4(al[mt][0], al[mt][1], al[mt][2], al[mt][3], sAl + off);
            }
            // consume B fragments immediately: only 4 B regs live at a time
#pragma unroll
            for (int nt = 0; nt < 4; nt++) {
                int row = wn + nt * 8 + b_row_lo;
                uint32_t off = tile_off(row, k16 * 2 + b_chunk_hi);
                uint32_t bh0, bh1, bl0, bl1;
                LDSM_X2(bh0, bh1, sWh + off);
                LDSM_X2(bl0, bl1, sWl + off);
#pragma unroll
                for (int mt = 0; mt < 4; mt++) {
                    MMA16816(c[mt][nt][0], c[mt][nt][1], c[mt][nt][2], c[mt][nt][3],
                             ah[mt][0], ah[mt][1], ah[mt][2], ah[mt][3], bh0, bh1);
                    MMA16816(c[mt][nt][0], c[mt][nt][1], c[mt][nt][2], c[mt][nt][3],
                             ah[mt][0], ah[mt][1], ah[mt][2], ah[mt][3], bl0, bl1);
                    MMA16816(c[mt][nt][0], c[mt][nt][1], c[mt][nt][2], c[mt][nt][3],
                             al[mt][0], al[mt][1], al[mt][2], al[mt][3], bh0, bh1);
                }
            }
        }
    }

    // epilogue: c frag -> global
    const int erow = lane >> 2;
    const int ecol = (lane & 3) * 2;
#pragma unroll
    for (int mt = 0; mt < 4; mt++) {
#pragma unroll
        for (int nt = 0; nt < 4; nt++) {
            int m = bm + wm + mt * 16 + erow;
            int n = bn + wn + nt * 8 + ecol;
            float* p0 = C + (size_t)m * DDIM + n;
            float* p1 = C + (size_t)(m + 8) * DDIM + n;
            *reinterpret_cast<float2*>(p0) = make_float2(c[mt][nt][0], c[mt][nt][1]);
            *reinterpret_cast<float2*>(p1) = make_float2(c[mt][nt][2], c[mt][nt][3]);
        }
    }
}

// ---------------- kv partial: 512-row S chunks ----------------
__global__ __launch_bounds__(256) void kv_partial_kernel(
    const float* __restrict__ k, const float* __restrict__ v,
    float* __restrict__ kvp, float* __restrict__ ksump, float* __restrict__ vsump)
{
    const int bh = blockIdx.x;       // 0..31
    const int chunk = blockIdx.y;    // 0..7
    const int b = bh >> 3, h = bh & 7;
    const size_t rowbase = ((size_t)(b * SS + chunk * CHUNK_S)) * DDIM + h * 128;

    __shared__ float ks[16][128];
    __shared__ float vs[16][128];
    const int tid = threadIdx.x;
    const int ty = tid >> 4, tx = tid & 15;
    const int lr = tid >> 4;
    const int lc = (tid & 15) << 3;

    float acc[8][8];
#pragma unroll
    for (int i = 0; i < 8; i++)
#pragma unroll
        for (int j = 0; j < 8; j++) acc[i][j] = 0.f;
    float sacc = 0.f;

    for (int sc = 0; sc < CHUNK_S / 16; sc++) {
        size_t base = rowbase + (size_t)(sc * 16 + lr) * DDIM + lc;
        float4 ka = *reinterpret_cast<const float4*>(k + base);
        float4 kb2 = *reinterpret_cast<const float4*>(k + base + 4);
        ks[lr][lc + 0] = ka.x; ks[lr][lc + 1] = ka.y; ks[lr][lc + 2] = ka.z; ks[lr][lc + 3] = ka.w;
        ks[lr][lc + 4] = kb2.x; ks[lr][lc + 5] = kb2.y; ks[lr][lc + 6] = kb2.z; ks[lr][lc + 7] = kb2.w;
        float4 va = *reinterpret_cast<const float4*>(v + base);
        float4 vb2 = *reinterpret_cast<const float4*>(v + base + 4);
        vs[lr][lc + 0] = va.x; vs[lr][lc + 1] = va.y; vs[lr][lc + 2] = va.z; vs[lr][lc + 3] = va.w;
        vs[lr][lc + 4] = vb2.x; vs[lr][lc + 5] = vb2.y; vs[lr][lc + 6] = vb2.z; vs[lr][lc + 7] = vb2.w;
        __syncthreads();
#pragma unroll
        for (int ssi = 0; ssi < 16; ssi++) {
            float4 a0 = *reinterpret_cast<const float4*>(&ks[ssi][ty * 8]);
            float4 a1 = *reinterpret_cast<const float4*>(&ks[ssi][ty * 8 + 4]);
            float4 b0 = *reinterpret_cast<const float4*>(&vs[ssi][tx * 8]);
            float4 b1 = *reinterpret_cast<const float4*>(&vs[ssi][tx * 8 + 4]);
            float af[8] = {a0.x, a0.y, a0.z, a0.w, a1.x, a1.y, a1.z, a1.w};
            float bf[8] = {b0.x, b0.y, b0.z, b0.w, b1.x, b1.y, b1.z, b1.w};
#pragma unroll
            for (int i = 0; i < 8; i++)
#pragma unroll
                for (int j = 0; j < 8; j++) acc[i][j] += af[i] * bf[j];
        }
        if (tid < 128) {
#pragma unroll
            for (int ssi = 0; ssi < 16; ssi++) sacc += ks[ssi][tid];
        } else {
#pragma unroll
            for (int ssi = 0; ssi < 16; ssi++) sacc += vs[ssi][tid - 128];
        }
        __syncthreads();
    }

    size_t outbase = ((size_t)(bh * NCHUNK + chunk)) * 16384;
#pragma unroll
    for (int i = 0; i < 8; i++) {
        float* p = kvp + outbase + (size_t)(ty * 8 + i) * 128 + tx * 8;
        *reinterpret_cast<float4*>(p) = make_float4(acc[i][0], acc[i][1], acc[i][2], acc[i][3]);
        *reinterpret_cast<float4*>(p + 4) = make_float4(acc[i][4], acc[i][5], acc[i][6], acc[i][7]);
    }
    if (tid < 128) ksump[(bh * NCHUNK + chunk) * 128 + tid] = sacc;
    else           vsump[(bh * NCHUNK + chunk) * 128 + (tid - 128)] = sacc;
}

__global__ void kv_reduce_kernel(const float* __restrict__ kvp, float* __restrict__ kv)
{
    int bh = blockIdx.y;
    int idx = blockIdx.x * 256 + threadIdx.x;
    const float* p = kvp + (size_t)bh * NCHUNK * 16384 + idx;
    float s = 0.f;
#pragma unroll
    for (int c = 0; c < NCHUNK; c++) s += p[(size_t)c * 16384];
    kv[(size_t)bh * 16384 + idx] = s;
}

__global__ void sum_reduce_kernel(const float* __restrict__ ksump, const float* __restrict__ vsump,
                                  float* __restrict__ ksum, float* __restrict__ vsum)
{
    int bh = blockIdx.x;
    int t = threadIdx.x;
    if (t < 128) {
        float s = 0.f;
#pragma unroll
        for (int c = 0; c < NCHUNK; c++) s += ksump[(bh * NCHUNK + c) * 128 + t];
        ksum[bh * 128 + t] = s;
    } else {
        int e = t - 128;
        float s = 0.f;
#pragma unroll
        for (int c = 0; c < NCHUNK; c++) s += vsump[(bh * NCHUNK + c) * 128 + e];
        vsum[bh * 128 + e] = s;
    }
}

// ---------------- attention + LePE + gate; emits bf16 hi/lo directly ----------------
__global__ __launch_bounds__(256) void attn_kernel(
    const float* __restrict__ q, const float* __restrict__ v,
    const float* __restrict__ gate, const float* __restrict__ kv,
    const float* __restrict__ ksum, const float* __restrict__ vsum,
    const float* __restrict__ lw, const float* __restrict__ lb,
    __nv_bfloat16* __restrict__ oh, __nv_bfloat16* __restrict__ ol)
{
    const int stile = blockIdx.x;
    const int bh = blockIdx.y;
    const int half = blockIdx.z;
    const int b = bh >> 3, h = bh & 7;
    const int s0 = stile * 16;
    const int e0 = half * 64;

    __shared__ float kvs[128][64];
    __shared__ float qs[16][128];
    __shared__ float ksums[128];
    __shared__ float vsums[64];
    __shared__ float dens[16];

    const int tid = threadIdx.x;
    for (int i = tid; i < 128 * 16; i += 256) {
        int d = i >> 4, c = (i & 15) << 2;
        float4 t = *reinterpret_cast<const float4*>(kv + (size_t)bh * 16384 + d * 128 + e0 + c);
        kvs[d][c] = t.x; kvs[d][c + 1] = t.y; kvs[d][c + 2] = t.z; kvs[d][c + 3] = t.w;
    }
    for (int i = tid; i < 16 * 32; i += 256) {
        int r = i >> 5, c = (i & 31) << 2;
        float4 t = *reinterpret_cast<const float4*>(
            q + (((size_t)(b * SS + s0 + r)) * HH + h) * 128 + c);
        qs[r][c] = t.x; qs[r][c + 1] = t.y; qs[r][c + 2] = t.z; qs[r][c + 3] = t.w;
    }
    if (tid < 128) ksums[tid] = ksum[bh * 128 + tid];
    else if (tid < 192) vsums[tid - 128] = vsum[bh * 128 + e0 + (tid - 128)];
    __syncthreads();

    if (tid < 16) {
        float ds = 0.f;
#pragma unroll
        for (int d = 0; d < 128; d++) ds += qs[tid][d] * ksums[d];
        dens[tid] = ds * SCALE + (float)SS;
    }
    __syncthreads();

    const int ss = tid >> 4;
    const int e4 = (tid & 15) << 2;
    float acc0 = 0.f, acc1 = 0.f, acc2 = 0.f, acc3 = 0.f;
#pragma unroll 4
    for (int d = 0; d < 128; d++) {
        float qv = qs[ss][d];
        float4 kvv = *reinterpret_cast<const float4*>(&kvs[d][e4]);
        acc0 += qv * kvv.x;
        acc1 += qv * kvv.y;
        acc2 += qv * kvv.z;
        acc3 += qv * kvv.w;
    }

    const float invden = 1.0f / dens[ss];
    const int sg = s0 + ss;
    const int cbase = h * 128 + e0 + e4;

    float a0 = (acc0 * SCALE + vsums[e4 + 0]) * invden;
    float a1 = (acc1 * SCALE + vsums[e4 + 1]) * invden;
    float a2 = (acc2 * SCALE + vsums[e4 + 2]) * invden;
    float a3 = (acc3 * SCALE + vsums[e4 + 3]) * invden;

    float lep0 = lb[cbase + 0], lep1 = lb[cbase + 1], lep2 = lb[cbase + 2], lep3 = lb[cbase + 3];
#pragma unroll
    for (int t = 0; t < 5; t++) {
        int sp = sg + t - 2;
        if (sp >= 0 && sp < SS) {
            float4 vv = *reinterpret_cast<const float4*>(
                v + (((size_t)(b * SS + sp)) * HH + h) * 128 + e0 + e4);
            lep0 += vv.x * lw[(cbase + 0) * 5 + t];
            lep1 += vv.y * lw[(cbase + 1) * 5 + t];
            lep2 += vv.z * lw[(cbase + 2) * 5 + t];
            lep3 += vv.w * lw[(cbase + 3) * 5 + t];
        }
    }

    float4 g4 = *reinterpret_cast<const float4*>(gate + ((size_t)(b * SS + sg)) * DDIM + cbase);
    float r0 = (a0 + lep0) * g4.x;
    float r1 = (a1 + lep1) * g4.y;
    float r2 = (a2 + lep2) * g4.z;
    float r3 = (a3 + lep3) * g4.w;

    __nv_bfloat16 h0 = __float2bfloat16(r0), h1 = __float2bfloat16(r1);
    __nv_bfloat16 h2 = __float2bfloat16(r2), h3 = __float2bfloat16(r3);
    __nv_bfloat16 l0 = __float2bfloat16(r0 - __bfloat162float(h0));
    __nv_bfloat16 l1 = __float2bfloat16(r1 - __bfloat162float(h1));
    __nv_bfloat16 l2 = __float2bfloat16(r2 - __bfloat162float(h2));
    __nv_bfloat16 l3 = __float2bfloat16(r3 - __bfloat162float(h3));
    size_t obase = ((size_t)(b * SS + sg)) * DDIM + cbase;
    __nv_bfloat162* hp = reinterpret_cast<__nv_bfloat162*>(oh + obase);
    __nv_bfloat162* lp = reinterpret_cast<__nv_bfloat162*>(ol + obase);
    hp[0] = __nv_bfloat162(h0, h1); hp[1] = __nv_bfloat162(h2, h3);
    lp[0] = __nv_bfloat162(l0, l1); lp[1] = __nv_bfloat162(l2, l3);
}

// ---------------- host launch ----------------
extern "C" void kernel_launch(void* const* d_in, const int* in_sizes, int n_in,
                              void* d_out, int out_size)
{
    const float* hs = (const float*)d_in[0];
    const float* Wq = (const float*)d_in[1];
    const float* Wk = (const float*)d_in[2];
    const float* Wv = (const float*)d_in[3];
    const float* Wg = (const float*)d_in[4];
    const float* Wo = (const float*)d_in[5];
    const float* lw = (const float*)d_in[6];
    const float* lb = (const float*)d_in[7];
    float* out = (float*)d_out;

    float *projp, *kvpp, *kspp, *vspp, *kvfull, *ksp, *vsp, *stp, *ctp;
    __nv_bfloat16 *hsh, *hsl, *oh, *ol, *wh, *wl;
    cudaGetSymbolAddress((void**)&projp, g_proj);
    cudaGetSymbolAddress((void**)&kvpp, g_kvp);
    cudaGetSymbolAddress((void**)&kspp, g_ksump);
    cudaGetSymbolAddress((void**)&vspp, g_vsump);
    cudaGetSymbolAddress((void**)&kvfull, g_kv);
    cudaGetSymbolAddress((void**)&ksp, g_ksum);
    cudaGetSymbolAddress((void**)&vsp, g_vsum);
    cudaGetSymbolAddress((void**)&hsh, g_hsh);
    cudaGetSymbolAddress((void**)&hsl, g_hsl);
    cudaGetSymbolAddress((void**)&oh, g_oh);
    cudaGetSymbolAddress((void**)&ol, g_ol);
    cudaGetSymbolAddress((void**)&wh, g_wh);
    cudaGetSymbolAddress((void**)&wl, g_wl);
    cudaGetSymbolAddress((void**)&stp, g_sintab);
    cudaGetSymbolAddress((void**)&ctp, g_costab);

    static int smem_set = 0;
    if (!smem_set) {
        cudaFuncSetAttribute(gemm_tc_kernel, cudaFuncAttributeMaxDynamicSharedMemorySize, SMEM_DYN);
        smem_set = 1;
    }

    float* qp = projp;
    float* kp = projp + (size_t)NM;
    float* vp = projp + 2 * (size_t)NM;
    float* gp = projp + 3 * (size_t)NM;

    const int WN4 = DDIM * DDIM / 4;
    const size_t WSZ = (size_t)DDIM * DDIM;
    // launch order arranged so gemm_qkvg is launch #6 (ncu -s 5 -c 1 captures it)
    rope_table_kernel<<<(SS * 64 + 255) / 256, 256>>>(stp, ctp);                       // 1
    split_kernel<<<NM / 4 / 256, 256>>>(hs, hsh, hsl, NM / 4);                         // 2
    split2_kernel<<<dim3(WN4 / 256, 2), 256>>>(Wq, Wk, wh, wl, wh + WSZ, wl + WSZ, WN4);          // 3
    split2_kernel<<<dim3(WN4 / 256, 2), 256>>>(Wv, Wg, wh + 2 * WSZ, wl + 2 * WSZ,
                                               wh + 3 * WSZ, wl + 3 * WSZ, WN4);       // 4
    split_kernel<<<WN4 / 256, 256>>>(Wo, wh + 4 * WSZ, wl + 4 * WSZ, WN4);             // 5

    // QKVG projection on tensor cores (launch #6 — profiled)
    gemm_tc_kernel<<<dim3(DDIM / 128, MM / 128, 4), 256, SMEM_DYN>>>(hsh, hsl, wh, wl, projp);

    rope_kernel<<<(MM * HH * 64 + 255) / 256, 256>>>(qp, kp, stp, ctp);                // 7

    kv_partial_kernel<<<dim3(BB * HH, NCHUNK), 256>>>(kp, vp, kvpp, kspp, vspp);       // 8
    kv_reduce_kernel<<<dim3(64, BB * HH), 256>>>(kvpp, kvfull);                        // 9
    sum_reduce_kernel<<<BB * HH, 256>>>(kspp, vspp, ksp, vsp);                         // 10

    attn_kernel<<<dim3(SS / 16, BB * HH, 2), 256>>>(qp, vp, gp, kvfull, ksp, vsp, lw, lb, oh, ol); // 11

    gemm_tc_kernel<<<dim3(DDIM / 128, MM / 128, 1), 256, SMEM_DYN>>>(                  // 12
        oh, ol, wh + 4 * WSZ, wl + 4 * WSZ, out);
}